// round 4
// baseline (speedup 1.0000x reference)
#include <cuda_runtime.h>
#include <cstdint>

#define BB 2
#define SS 2048
#define EE 1024
#define HH 16
#define DD 64
#define MM (BB * SS)
#define SCALE 0.125f
#define GK 1024
#define GN 1024

// ---------------- scratch ----------------
__device__ float g_Q[MM * EE];
__device__ float g_K[MM * EE];
__device__ float g_V[MM * EE];
__device__ float g_G[MM * EE];
__device__ float g_O[2 * MM * EE];

// ---------------- tf32 helpers ----------------
__device__ __forceinline__ float to_tf32(float x) {
    uint32_t u;
    asm("cvt.rna.tf32.f32 %0, %1;" : "=r"(u) : "f"(x));
    return __uint_as_float(u);
}
__device__ __forceinline__ void mma8(float* d, const uint32_t* a, const uint32_t* b) {
    asm volatile(
        "mma.sync.aligned.m16n8k8.row.col.f32.tf32.tf32.f32 "
        "{%0,%1,%2,%3}, {%4,%5,%6,%7}, {%8,%9}, {%0,%1,%2,%3};"
        : "+f"(d[0]), "+f"(d[1]), "+f"(d[2]), "+f"(d[3])
        : "r"(a[0]), "r"(a[1]), "r"(a[2]), "r"(a[3]), "r"(b[0]), "r"(b[1]));
}

// ---------------- GEMM: C = (A [+A2]) @ W + bias, tf32 tensor cores -------
// 128x128 tile, BK=32, 256 threads (8 warps), warp tile 64x32.
#define APAD 36
#define BPAD 132

__global__ __launch_bounds__(256, 2) void gemm_tf32(
    const float* __restrict__ A, const float* __restrict__ A2,
    const float* __restrict__ W, const float* __restrict__ bias,
    float* __restrict__ C)
{
    __shared__ float As[128 * APAD];  // As[m][k], pad 36
    __shared__ float Bs[32 * BPAD];   // Bs[k][n], pad 132

    const int tid = threadIdx.x;
    const int lane = tid & 31;
    const int wid = tid >> 5;
    const int wm = wid >> 2;       // 0..1
    const int wn = wid & 3;        // 0..3
    const int g = lane >> 2;       // 0..7
    const int c = lane & 3;        // 0..3
    const int row0 = blockIdx.y * 128;
    const int col0 = blockIdx.x * 128;

    float acc[4][4][4];
#pragma unroll
    for (int mi = 0; mi < 4; ++mi)
#pragma unroll
        for (int ni = 0; ni < 4; ++ni)
#pragma unroll
            for (int j = 0; j < 4; ++j) acc[mi][ni][j] = 0.f;

    for (int k0 = 0; k0 < GK; k0 += 32) {
        __syncthreads();
        // A tile: 128m x 32k = 1024 float4
#pragma unroll
        for (int u = 0; u < 4; ++u) {
            int idx = tid + u * 256;
            int m = idx >> 3;
            int kc = (idx & 7) << 2;
            float4 v = *(const float4*)&A[(size_t)(row0 + m) * GK + k0 + kc];
            if (A2) {
                float4 v2 = *(const float4*)&A2[(size_t)(row0 + m) * GK + k0 + kc];
                v.x += v2.x; v.y += v2.y; v.z += v2.z; v.w += v2.w;
            }
            v.x = to_tf32(v.x); v.y = to_tf32(v.y);
            v.z = to_tf32(v.z); v.w = to_tf32(v.w);
            *(float4*)&As[m * APAD + kc] = v;
        }
        // B tile: 32k x 128n = 1024 float4
#pragma unroll
        for (int u = 0; u < 4; ++u) {
            int idx = tid + u * 256;
            int kk = idx >> 5;
            int n4 = (idx & 31) << 2;
            float4 v = *(const float4*)&W[(size_t)(k0 + kk) * GN + col0 + n4];
            v.x = to_tf32(v.x); v.y = to_tf32(v.y);
            v.z = to_tf32(v.z); v.w = to_tf32(v.w);
            *(float4*)&Bs[kk * BPAD + n4] = v;
        }
        __syncthreads();

#pragma unroll
        for (int ks = 0; ks < 4; ++ks) {
            const int kb = ks * 8;
            uint32_t a[4][4], b[4][2];
#pragma unroll
            for (int mi = 0; mi < 4; ++mi) {
                int r = wm * 64 + mi * 16 + g;
                a[mi][0] = __float_as_uint(As[r * APAD + kb + c]);
                a[mi][1] = __float_as_uint(As[(r + 8) * APAD + kb + c]);
                a[mi][2] = __float_as_uint(As[r * APAD + kb + c + 4]);
                a[mi][3] = __float_as_uint(As[(r + 8) * APAD + kb + c + 4]);
            }
#pragma unroll
            for (int ni = 0; ni < 4; ++ni) {
                int n = wn * 32 + ni * 8 + g;
                b[ni][0] = __float_as_uint(Bs[(kb + c) * BPAD + n]);
                b[ni][1] = __float_as_uint(Bs[(kb + c + 4) * BPAD + n]);
            }
#pragma unroll
            for (int mi = 0; mi < 4; ++mi)
#pragma unroll
                for (int ni = 0; ni < 4; ++ni)
                    mma8(acc[mi][ni], a[mi], b[ni]);
        }
    }

    // epilogue
#pragma unroll
    for (int ni = 0; ni < 4; ++ni) {
        int col = col0 + wn * 32 + ni * 8 + 2 * c;
        float2 bv = make_float2(0.f, 0.f);
        if (bias) bv = *(const float2*)&bias[col];
#pragma unroll
        for (int mi = 0; mi < 4; ++mi) {
            int r = row0 + wm * 64 + mi * 16 + g;
            float2 o0 = make_float2(acc[mi][ni][0] + bv.x, acc[mi][ni][1] + bv.y);
            float2 o1 = make_float2(acc[mi][ni][2] + bv.x, acc[mi][ni][3] + bv.y);
            *(float2*)&C[(size_t)r * GN + col] = o0;
            *(float2*)&C[(size_t)(r + 8) * GN + col] = o1;
        }
    }
}

// ---------------- Attention: tf32 mma flash, one partition per block -------
// Grid (S/64, H, B*2). Block 128 threads (4 warps); warp owns 16 q rows.
#define SP 68
#define ATT_SMEM_FLOATS (4 * 64 * SP + 64)
#define ATT_SMEM_BYTES (ATT_SMEM_FLOATS * 4)

__global__ __launch_bounds__(128, 2) void attn_tf32(
    const float* __restrict__ Q, const float* __restrict__ K,
    const float* __restrict__ V, const float* __restrict__ G,
    const unsigned char* __restrict__ mask, float* __restrict__ O)
{
    extern __shared__ float sm[];
    float* Qs = sm;                 // [64][SP]
    float* Ks = sm + 64 * SP;       // [64][SP]
    float* Vs = sm + 2 * 64 * SP;   // [64][SP]
    float* Ps = sm + 3 * 64 * SP;   // [64][SP]
    float* msk = sm + 4 * 64 * SP;  // [64]

    const int tid = threadIdx.x;
    const int lane = tid & 31;
    const int wid = tid >> 5;
    const int g = lane >> 2;
    const int c = lane & 3;
    const int qt = blockIdx.x;
    const int h = blockIdx.y;
    const int z = blockIdx.z;
    const int b = z >> 1;
    const int p = z & 1;
    const int q0 = qt * 64;
    const int hoff = h * DD;
    const int kbase = p * 1024;
    const float pw = p ? 1.0f : 0.5f;   // partition_weight / num_partitions
    const int wrow = wid * 16;

    // load Q tile (pre-scaled by SCALE, tf32)
#pragma unroll
    for (int u = 0; u < 8; ++u) {
        int idx = tid + u * 128;
        int r = idx >> 4;
        int d4 = (idx & 15) << 2;
        float4 v = *(const float4*)&Q[((size_t)(b * SS + q0 + r)) * EE + hoff + d4];
        v.x = to_tf32(v.x * SCALE); v.y = to_tf32(v.y * SCALE);
        v.z = to_tf32(v.z * SCALE); v.w = to_tf32(v.w * SCALE);
        *(float4*)&Qs[r * SP + d4] = v;
    }

    float o[8][4];
#pragma unroll
    for (int ni = 0; ni < 8; ++ni)
#pragma unroll
        for (int j = 0; j < 4; ++j) o[ni][j] = 0.f;
    float l0 = 0.f, l1 = 0.f;

#pragma unroll 1
    for (int t = 0; t < 16; ++t) {
        const int k0g = kbase + t * 64;
        __syncthreads();
#pragma unroll
        for (int u = 0; u < 8; ++u) {
            int idx = tid + u * 128;
            int r = idx >> 4;
            int d4 = (idx & 15) << 2;
            size_t gidx = ((size_t)(b * SS + k0g + r)) * EE + hoff + d4;
            float4 kv = *(const float4*)&K[gidx];
            kv.x = to_tf32(kv.x); kv.y = to_tf32(kv.y);
            kv.z = to_tf32(kv.z); kv.w = to_tf32(kv.w);
            *(float4*)&Ks[r * SP + d4] = kv;
            float4 vv = *(const float4*)&V[gidx];
            vv.x = to_tf32(vv.x); vv.y = to_tf32(vv.y);
            vv.z = to_tf32(vv.z); vv.w = to_tf32(vv.w);
            *(float4*)&Vs[r * SP + d4] = vv;
        }
        if (tid < 64) msk[tid] = mask[(size_t)b * SS + k0g + tid] ? -1e30f : 0.f;
        __syncthreads();

        // ---- scores = Q @ K^T (pre-scaled) ----
        float s[8][4];
#pragma unroll
        for (int ni = 0; ni < 8; ++ni)
#pragma unroll
            for (int j = 0; j < 4; ++j) s[ni][j] = 0.f;

#pragma unroll
        for (int ds = 0; ds < 8; ++ds) {
            uint32_t a[4];
            int r = wrow + g;
            a[0] = __float_as_uint(Qs[r * SP + ds * 8 + c]);
            a[1] = __float_as_uint(Qs[(r + 8) * SP + ds * 8 + c]);
            a[2] = __float_as_uint(Qs[r * SP + ds * 8 + c + 4]);
            a[3] = __float_as_uint(Qs[(r + 8) * SP + ds * 8 + c + 4]);
#pragma unroll
            for (int ni = 0; ni < 8; ++ni) {
                uint32_t bf[2];
                bf[0] = __float_as_uint(Ks[(ni * 8 + g) * SP + ds * 8 + c]);
                bf[1] = __float_as_uint(Ks[(ni * 8 + g) * SP + ds * 8 + c + 4]);
                mma8(s[ni], a, bf);
            }
        }

        // ---- softmax (no max subtraction; logits bounded) ----
        float rs0 = 0.f, rs1 = 0.f;
#pragma unroll
        for (int ni = 0; ni < 8; ++ni) {
            float m0 = msk[ni * 8 + 2 * c];
            float m1 = msk[ni * 8 + 2 * c + 1];
            float e0 = __expf(s[ni][0] + m0);
            float e1 = __expf(s[ni][1] + m1);
            float e2 = __expf(s[ni][2] + m0);
            float e3 = __expf(s[ni][3] + m1);
            rs0 += e0 + e1;
            rs1 += e2 + e3;
            float2 p0 = make_float2(to_tf32(e0), to_tf32(e1));
            float2 p1 = make_float2(to_tf32(e2), to_tf32(e3));
            *(float2*)&Ps[(wrow + g) * SP + ni * 8 + 2 * c] = p0;
            *(float2*)&Ps[(wrow + g + 8) * SP + ni * 8 + 2 * c] = p1;
        }
        rs0 += __shfl_xor_sync(0xffffffffu, rs0, 1);
        rs0 += __shfl_xor_sync(0xffffffffu, rs0, 2);
        rs1 += __shfl_xor_sync(0xffffffffu, rs1, 1);
        rs1 += __shfl_xor_sync(0xffffffffu, rs1, 2);
        l0 += rs0;
        l1 += rs1;
        __syncwarp();

        // ---- out += P @ V ----
#pragma unroll
        for (int ks = 0; ks < 8; ++ks) {
            uint32_t a[4];
            int r = wrow + g;
            a[0] = __float_as_uint(Ps[r * SP + ks * 8 + c]);
            a[1] = __float_as_uint(Ps[(r + 8) * SP + ks * 8 + c]);
            a[2] = __float_as_uint(Ps[r * SP + ks * 8 + c + 4]);
            a[3] = __float_as_uint(Ps[(r + 8) * SP + ks * 8 + c + 4]);
#pragma unroll
            for (int ni = 0; ni < 8; ++ni) {
                uint32_t bf[2];
                bf[0] = __float_as_uint(Vs[(ks * 8 + c) * SP + ni * 8 + g]);
                bf[1] = __float_as_uint(Vs[(ks * 8 + c + 4) * SP + ni * 8 + g]);
                mma8(o[ni], a, bf);
            }
        }
    }

    // ---- epilogue: normalize, gate, store to partition buffer ----
    float* Op = O + (size_t)p * MM * EE;
    const float inv0 = pw / l0;
    const float inv1 = pw / l1;
    const int r0 = q0 + wrow + g;
    const int r1 = r0 + 8;
#pragma unroll
    for (int ni = 0; ni < 8; ++ni) {
        int col = hoff + ni * 8 + 2 * c;
        size_t i0 = (size_t)(b * SS + r0) * EE + col;
        size_t i1 = (size_t)(b * SS + r1) * EE + col;
        float2 v0 = make_float2(o[ni][0] * inv0, o[ni][1] * inv0);
        float2 v1 = make_float2(o[ni][2] * inv1, o[ni][3] * inv1);
        if (r0 >= 1) {
            float2 gv = *(const float2*)&G[i0];
            v0.x *= 1.f / (1.f + __expf(-gv.x));
            v0.y *= 1.f / (1.f + __expf(-gv.y));
        }
        {
            float2 gv = *(const float2*)&G[i1];   // r1 >= 8 always gated
            v1.x *= 1.f / (1.f + __expf(-gv.x));
            v1.y *= 1.f / (1.f + __expf(-gv.y));
        }
        *(float2*)&Op[i0] = v0;
        *(float2*)&Op[i1] = v1;
    }
}

// ---------------- launch ----------------
extern "C" void kernel_launch(void* const* d_in, const int* in_sizes, int n_in,
                              void* d_out, int out_size)
{
    const float* x  = (const float*)d_in[0];
    const float* Wq = (const float*)d_in[1];
    const float* bq = (const float*)d_in[2];
    const float* Wk = (const float*)d_in[3];
    const float* bk = (const float*)d_in[4];
    const float* Wv = (const float*)d_in[5];
    const float* bv = (const float*)d_in[6];
    const float* Wo = (const float*)d_in[7];
    const float* bo = (const float*)d_in[8];
    const float* Wg = (const float*)d_in[9];
    const unsigned char* mask = (const unsigned char*)d_in[10];
    float* out = (float*)d_out;

    float *Qp, *Kp, *Vp, *Gp, *Op;
    cudaGetSymbolAddress((void**)&Qp, g_Q);
    cudaGetSymbolAddress((void**)&Kp, g_K);
    cudaGetSymbolAddress((void**)&Vp, g_V);
    cudaGetSymbolAddress((void**)&Gp, g_G);
    cudaGetSymbolAddress((void**)&Op, g_O);

    static int attn_smem_set = 0;
    if (!attn_smem_set) {
        cudaFuncSetAttribute(attn_tf32, cudaFuncAttributeMaxDynamicSharedMemorySize, ATT_SMEM_BYTES);
        attn_smem_set = 1;
    }

    dim3 ggrid(GN / 128, MM / 128);
    gemm_tf32<<<ggrid, 256>>>(x, nullptr, Wq, bq, Qp);
    gemm_tf32<<<ggrid, 256>>>(x, nullptr, Wk, bk, Kp);
    gemm_tf32<<<ggrid, 256>>>(x, nullptr, Wv, bv, Vp);
    gemm_tf32<<<ggrid, 256>>>(x, nullptr, Wg, nullptr, Gp);

    dim3 agrid(SS / 64, HH, BB * 2);
    attn_tf32<<<agrid, 128, ATT_SMEM_BYTES>>>(Qp, Kp, Vp, Gp, mask, Op);

    gemm_tf32<<<ggrid, 256>>>(Op, Op + (size_t)MM * EE, Wo, bo, out);
}

// round 5
// speedup vs baseline: 2.1644x; 2.1644x over previous
#include <cuda_runtime.h>
#include <cuda_fp16.h>
#include <cstdint>

#define BB 2
#define SS 2048
#define EE 1024
#define HH 16
#define DD 64
#define MM (BB*SS)
#define SCALE 0.125f
#define GK 1024
#define GN 1024

// ---------------- scratch ----------------
__device__ __half g_Xh[MM*EE];
__device__ __half g_WT[5][EE*EE];   // 0=q 1=k 2=v 3=g 4=o, [n][k]
__device__ __half g_Qh[MM*EE];
__device__ __half g_Kh[MM*EE];
__device__ __half g_Vt[MM*EE];      // [b][h][d][tok]
__device__ float  g_G[MM*EE];
__device__ __half g_Oh[MM*EE];

// ---------------- helpers ----------------
__device__ __forceinline__ uint32_t smem_u32(const void* p) {
    return (uint32_t)__cvta_generic_to_shared(p);
}
#define CP16(d_, s_) asm volatile("cp.async.cg.shared.global [%0],[%1],16;\n" :: "r"(d_), "l"(s_))
#define CPCOMMIT() asm volatile("cp.async.commit_group;\n")
#define CPWAIT1() asm volatile("cp.async.wait_group 1;\n")
#define CPWAIT0() asm volatile("cp.async.wait_group 0;\n")

__device__ __forceinline__ void mma16(float* d, const uint32_t* a, const uint32_t* b) {
    asm volatile(
        "mma.sync.aligned.m16n8k16.row.col.f32.f16.f16.f32 "
        "{%0,%1,%2,%3}, {%4,%5,%6,%7}, {%8,%9}, {%0,%1,%2,%3};"
        : "+f"(d[0]), "+f"(d[1]), "+f"(d[2]), "+f"(d[3])
        : "r"(a[0]), "r"(a[1]), "r"(a[2]), "r"(a[3]), "r"(b[0]), "r"(b[1]));
}

// ---------------- prep ----------------
__global__ void prep_x(const float* __restrict__ x) {
    int i = blockIdx.x * 256 + threadIdx.x;
    float2 v = ((const float2*)x)[i];
    ((__half2*)g_Xh)[i] = __floats2half2_rn(v.x, v.y);
}
__global__ void prep_w(const float* Wq, const float* Wk, const float* Wv,
                       const float* Wg, const float* Wo) {
    __shared__ float t[32][33];
    int z = blockIdx.z;
    const float* W = z==0?Wq : z==1?Wk : z==2?Wv : z==3?Wg : Wo;
    __half* D = g_WT[z];
    int n0 = blockIdx.x*32, k0 = blockIdx.y*32;
    int tx = threadIdx.x, ty = threadIdx.y;
#pragma unroll
    for (int j = 0; j < 4; ++j)
        t[ty + j*8][tx] = W[(size_t)(k0 + ty + j*8)*GN + n0 + tx];
    __syncthreads();
#pragma unroll
    for (int j = 0; j < 4; ++j)
        D[(size_t)(n0 + ty + j*8)*GK + k0 + tx] = __float2half_rn(t[tx][ty + j*8]);
}

// ---------------- GEMM core: C = A(h)[M,K] @ Bt(h)[N,K]^T ----------------
// 128x128x64 tile, 128 threads (4 warps 2x2), warp tile 64x64, cp.async x2.
#define AST 72
#define TILE_H (128*AST)
#define GEMM_SMEM (4*TILE_H*2)

__device__ __forceinline__ void gemm_core(
    const __half* __restrict__ A, const __half* __restrict__ Bt,
    const float* __restrict__ bias, float* __restrict__ fC,
    __half* __restrict__ hC, int mode)
{
    extern __shared__ char smp[];
    __half* As = (__half*)smp;
    __half* Bs = (__half*)smp + 2*TILE_H;

    const int tid = threadIdx.x, lane = tid & 31, wid = tid >> 5;
    const int wm = wid >> 1, wn = wid & 1, g = lane >> 2, c = lane & 3;
    const int row0 = blockIdx.y*128, col0 = blockIdx.x*128;

    float acc[4][8][4];
#pragma unroll
    for (int mi = 0; mi < 4; ++mi)
#pragma unroll
        for (int ni = 0; ni < 8; ++ni) {
            acc[mi][ni][0]=0.f; acc[mi][ni][1]=0.f; acc[mi][ni][2]=0.f; acc[mi][ni][3]=0.f;
        }

#pragma unroll 1
    for (int pre = 0; pre < 1; ++pre) {  // issue tile 0
#pragma unroll
        for (int u = 0; u < 8; ++u) {
            int idx = tid + u*128, m = idx >> 3, ko = (idx & 7)*8;
            CP16(smem_u32(&As[m*AST + ko]), &A[(size_t)(row0+m)*GK + ko]);
            CP16(smem_u32(&Bs[m*AST + ko]), &Bt[(size_t)(col0+m)*GK + ko]);
        }
        CPCOMMIT();
    }

#pragma unroll 1
    for (int it = 0; it < 16; ++it) {
        if (it < 15) {
            int buf = (it+1) & 1, k0 = (it+1)*64;
#pragma unroll
            for (int u = 0; u < 8; ++u) {
                int idx = tid + u*128, m = idx >> 3, ko = (idx & 7)*8;
                CP16(smem_u32(&As[buf*TILE_H + m*AST + ko]), &A[(size_t)(row0+m)*GK + k0 + ko]);
                CP16(smem_u32(&Bs[buf*TILE_H + m*AST + ko]), &Bt[(size_t)(col0+m)*GK + k0 + ko]);
            }
            CPCOMMIT();
            CPWAIT1();
        } else {
            CPWAIT0();
        }
        __syncthreads();
        const __half* Ab = &As[(it & 1)*TILE_H];
        const __half* Bb = &Bs[(it & 1)*TILE_H];
#pragma unroll
        for (int ks = 0; ks < 4; ++ks) {
            int kb = ks*16;
            uint32_t a[4][4];
#pragma unroll
            for (int mi = 0; mi < 4; ++mi) {
                int r = wm*64 + mi*16 + g;
                a[mi][0] = *(const uint32_t*)&Ab[r*AST + kb + 2*c];
                a[mi][1] = *(const uint32_t*)&Ab[(r+8)*AST + kb + 2*c];
                a[mi][2] = *(const uint32_t*)&Ab[r*AST + kb + 8 + 2*c];
                a[mi][3] = *(const uint32_t*)&Ab[(r+8)*AST + kb + 8 + 2*c];
            }
#pragma unroll
            for (int ni = 0; ni < 8; ++ni) {
                int n = wn*64 + ni*8 + g;
                uint32_t b[2];
                b[0] = *(const uint32_t*)&Bb[n*AST + kb + 2*c];
                b[1] = *(const uint32_t*)&Bb[n*AST + kb + 8 + 2*c];
#pragma unroll
                for (int mi = 0; mi < 4; ++mi) mma16(acc[mi][ni], a[mi], b);
            }
        }
        __syncthreads();
    }

    // epilogue
#pragma unroll
    for (int mi = 0; mi < 4; ++mi) {
#pragma unroll
        for (int ni = 0; ni < 8; ++ni) {
            int r = row0 + wm*64 + mi*16 + g;
            int col = col0 + wn*64 + ni*8 + 2*c;
            float b0 = 0.f, b1 = 0.f;
            if (bias) { b0 = bias[col]; b1 = bias[col+1]; }
            float v0 = acc[mi][ni][0]+b0, v1 = acc[mi][ni][1]+b1;
            float v2 = acc[mi][ni][2]+b0, v3 = acc[mi][ni][3]+b1;
            if (mode == 0) { v0*=SCALE; v1*=SCALE; v2*=SCALE; v3*=SCALE; }
            if (mode >= 3) {         // float out (G or final)
                *(float2*)&fC[(size_t)r*GN + col] = make_float2(v0, v1);
                *(float2*)&fC[(size_t)(r+8)*GN + col] = make_float2(v2, v3);
            } else if (mode == 2) {  // V transposed: [b][h][d][tok]
                int bi = r >> 11, tok = r & 2047, hh = col >> 6, d = col & 63;
                __half* Vb = &g_Vt[(size_t)((bi*HH + hh)*DD) * SS];
                Vb[(size_t)d*SS + tok]       = __float2half_rn(v0);
                Vb[(size_t)(d+1)*SS + tok]   = __float2half_rn(v1);
                Vb[(size_t)d*SS + tok+8]     = __float2half_rn(v2);
                Vb[(size_t)(d+1)*SS + tok+8] = __float2half_rn(v3);
            } else {                 // half out (Q or K)
                *(__half2*)&hC[(size_t)r*GN + col] = __floats2half2_rn(v0, v1);
                *(__half2*)&hC[(size_t)(r+8)*GN + col] = __floats2half2_rn(v2, v3);
            }
        }
    }
}

__global__ __launch_bounds__(128) void gemm_qkvg(
    const float* bq, const float* bk, const float* bv)
{
    int z = blockIdx.z;
    const float* bias = z==0?bq : z==1?bk : z==2?bv : nullptr;
    float* fC = (z == 3) ? g_G : nullptr;
    __half* hC = z==0?g_Qh : z==1?g_Kh : nullptr;
    gemm_core(g_Xh, g_WT[z], bias, fC, hC, z);
}
__global__ __launch_bounds__(128) void gemm_out(const float* bo, float* out)
{
    gemm_core(g_Oh, g_WT[4], bo, out, nullptr, 4);
}

// ---------------- Attention: fp16 mma flash, both partitions per block ----
// Grid (S/64, H, B). 128 threads (4 warps), warp = 16 q rows, 64-key tiles.
#define SP2 72
#define ATT_SMEM ((4*64*SP2)*2 + 64*4)

__global__ __launch_bounds__(128) void attn_h(const unsigned char* __restrict__ mask)
{
    extern __shared__ char smc[];
    __half* Qs = (__half*)smc;                  // [64][SP2]
    __half* Ks = (__half*)smc + 64*SP2;
    __half* Vs = (__half*)smc + 2*64*SP2;       // Vt: [d][k]
    __half* Ps = (__half*)smc + 3*64*SP2;
    float* msk = (float*)(smc + 8*64*SP2);      // [64]

    const int tid = threadIdx.x, lane = tid & 31, wid = tid >> 5;
    const int g = lane >> 2, c = lane & 3;
    const int h = blockIdx.y, b = blockIdx.z;
    const int q0 = blockIdx.x*64, hoff = h*DD;
    const int wrow = wid*16;

    // load Q tile (pre-scaled in GEMM)
#pragma unroll
    for (int u = 0; u < 4; ++u) {
        int idx = tid + u*128, r = idx >> 3, ko = (idx & 7)*8;
        *(uint4*)&Qs[r*SP2 + ko] =
            *(const uint4*)&g_Qh[(size_t)(b*SS + q0 + r)*EE + hoff + ko];
    }

    float fin[8][4];
#pragma unroll
    for (int ni = 0; ni < 8; ++ni) { fin[ni][0]=0.f; fin[ni][1]=0.f; fin[ni][2]=0.f; fin[ni][3]=0.f; }

#pragma unroll 1
    for (int p = 0; p < 2; ++p) {
        const int kbase = p*1024;
        const float pw = p ? 1.0f : 0.5f;
        float l0 = 0.f, l1 = 0.f;
        float o[8][4];
#pragma unroll
        for (int ni = 0; ni < 8; ++ni) { o[ni][0]=0.f; o[ni][1]=0.f; o[ni][2]=0.f; o[ni][3]=0.f; }

#pragma unroll 1
        for (int t = 0; t < 16; ++t) {
            const int k0g = kbase + t*64;
            __syncthreads();
#pragma unroll
            for (int u = 0; u < 4; ++u) {
                int idx = tid + u*128, r = idx >> 3, ko = (idx & 7)*8;
                *(uint4*)&Ks[r*SP2 + ko] =
                    *(const uint4*)&g_Kh[(size_t)(b*SS + k0g + r)*EE + hoff + ko];
                *(uint4*)&Vs[r*SP2 + ko] =
                    *(const uint4*)&g_Vt[(size_t)((b*HH + h)*DD + r)*SS + k0g + ko];
            }
            if (tid < 64) msk[tid] = mask[(size_t)b*SS + k0g + tid] ? -1e30f : 0.f;
            __syncthreads();

            // scores = Q @ K^T
            float s[8][4];
#pragma unroll
            for (int ni = 0; ni < 8; ++ni) { s[ni][0]=0.f; s[ni][1]=0.f; s[ni][2]=0.f; s[ni][3]=0.f; }
#pragma unroll
            for (int ks = 0; ks < 4; ++ks) {
                int kb = ks*16;
                uint32_t a[4];
                int r = wrow + g;
                a[0] = *(const uint32_t*)&Qs[r*SP2 + kb + 2*c];
                a[1] = *(const uint32_t*)&Qs[(r+8)*SP2 + kb + 2*c];
                a[2] = *(const uint32_t*)&Qs[r*SP2 + kb + 8 + 2*c];
                a[3] = *(const uint32_t*)&Qs[(r+8)*SP2 + kb + 8 + 2*c];
#pragma unroll
                for (int ni = 0; ni < 8; ++ni) {
                    int n = ni*8 + g;
                    uint32_t bf[2];
                    bf[0] = *(const uint32_t*)&Ks[n*SP2 + kb + 2*c];
                    bf[1] = *(const uint32_t*)&Ks[n*SP2 + kb + 8 + 2*c];
                    mma16(s[ni], a, bf);
                }
            }

            // softmax (no max subtraction; logits bounded)
            float rs0 = 0.f, rs1 = 0.f;
#pragma unroll
            for (int ni = 0; ni < 8; ++ni) {
                float m0 = msk[ni*8 + 2*c], m1 = msk[ni*8 + 2*c + 1];
                float e0 = __expf(s[ni][0] + m0), e1 = __expf(s[ni][1] + m1);
                float e2 = __expf(s[ni][2] + m0), e3 = __expf(s[ni][3] + m1);
                rs0 += e0 + e1; rs1 += e2 + e3;
                *(__half2*)&Ps[(wrow+g)*SP2 + ni*8 + 2*c] = __floats2half2_rn(e0, e1);
                *(__half2*)&Ps[(wrow+g+8)*SP2 + ni*8 + 2*c] = __floats2half2_rn(e2, e3);
            }
            rs0 += __shfl_xor_sync(0xffffffffu, rs0, 1);
            rs0 += __shfl_xor_sync(0xffffffffu, rs0, 2);
            rs1 += __shfl_xor_sync(0xffffffffu, rs1, 1);
            rs1 += __shfl_xor_sync(0xffffffffu, rs1, 2);
            l0 += rs0; l1 += rs1;
            __syncwarp();

            // o += P @ V^T   (Vs[d][k], B frag from [n=d][k])
#pragma unroll
            for (int ks = 0; ks < 4; ++ks) {
                int kb = ks*16;
                uint32_t a[4];
                int r = wrow + g;
                a[0] = *(const uint32_t*)&Ps[r*SP2 + kb + 2*c];
                a[1] = *(const uint32_t*)&Ps[(r+8)*SP2 + kb + 2*c];
                a[2] = *(const uint32_t*)&Ps[r*SP2 + kb + 8 + 2*c];
                a[3] = *(const uint32_t*)&Ps[(r+8)*SP2 + kb + 8 + 2*c];
#pragma unroll
                for (int ni = 0; ni < 8; ++ni) {
                    int n = ni*8 + g;
                    uint32_t bf[2];
                    bf[0] = *(const uint32_t*)&Vs[n*SP2 + kb + 2*c];
                    bf[1] = *(const uint32_t*)&Vs[n*SP2 + kb + 8 + 2*c];
                    mma16(o[ni], a, bf);
                }
            }
            __syncwarp();
        }
        float inv0 = pw / l0, inv1 = pw / l1;
#pragma unroll
        for (int ni = 0; ni < 8; ++ni) {
            fin[ni][0] += o[ni][0]*inv0; fin[ni][1] += o[ni][1]*inv0;
            fin[ni][2] += o[ni][2]*inv1; fin[ni][3] += o[ni][3]*inv1;
        }
    }

    // epilogue: gate, write half
    const int r0 = q0 + wrow + g, r1 = r0 + 8;
#pragma unroll
    for (int ni = 0; ni < 8; ++ni) {
        int col = hoff + ni*8 + 2*c;
        size_t i0 = (size_t)(b*SS + r0)*EE + col;
        size_t i1 = (size_t)(b*SS + r1)*EE + col;
        float v0 = fin[ni][0], v1 = fin[ni][1], v2 = fin[ni][2], v3 = fin[ni][3];
        if (r0 >= 1) {
            float2 gv = *(const float2*)&g_G[i0];
            v0 *= 1.f/(1.f + __expf(-gv.x));
            v1 *= 1.f/(1.f + __expf(-gv.y));
        }
        float2 gw = *(const float2*)&g_G[i1];
        v2 *= 1.f/(1.f + __expf(-gw.x));
        v3 *= 1.f/(1.f + __expf(-gw.y));
        *(__half2*)&g_Oh[i0] = __floats2half2_rn(v0, v1);
        *(__half2*)&g_Oh[i1] = __floats2half2_rn(v2, v3);
    }
}

// ---------------- launch ----------------
extern "C" void kernel_launch(void* const* d_in, const int* in_sizes, int n_in,
                              void* d_out, int out_size)
{
    const float* x  = (const float*)d_in[0];
    const float* Wq = (const float*)d_in[1];
    const float* bq = (const float*)d_in[2];
    const float* Wk = (const float*)d_in[3];
    const float* bk = (const float*)d_in[4];
    const float* Wv = (const float*)d_in[5];
    const float* bv = (const float*)d_in[6];
    const float* Wo = (const float*)d_in[7];
    const float* bo = (const float*)d_in[8];
    const float* Wg = (const float*)d_in[9];
    const unsigned char* mask = (const unsigned char*)d_in[10];
    float* out = (float*)d_out;

    static int attr_set = 0;
    if (!attr_set) {
        cudaFuncSetAttribute(gemm_qkvg, cudaFuncAttributeMaxDynamicSharedMemorySize, GEMM_SMEM);
        cudaFuncSetAttribute(gemm_out,  cudaFuncAttributeMaxDynamicSharedMemorySize, GEMM_SMEM);
        cudaFuncSetAttribute(attn_h,    cudaFuncAttributeMaxDynamicSharedMemorySize, ATT_SMEM);
        attr_set = 1;
    }

    prep_x<<<MM*EE/512, 256>>>(x);
    prep_w<<<dim3(32, 32, 5), dim3(32, 8)>>>(Wq, Wk, Wv, Wg, Wo);
    gemm_qkvg<<<dim3(8, 32, 4), 128, GEMM_SMEM>>>(bq, bk, bv);
    attn_h<<<dim3(SS/64, HH, BB), 128, ATT_SMEM>>>(mask);
    gemm_out<<<dim3(8, 32), 128, GEMM_SMEM>>>(bo, out);
}

// round 7
// speedup vs baseline: 2.4742x; 1.1432x over previous
#include <cuda_runtime.h>
#include <cuda_fp16.h>
#include <cstdint>

#define BB 2
#define SS 2048
#define EE 1024
#define HH 16
#define DD 64
#define MM (BB*SS)
#define SCALE 0.125f
#define GK 1024
#define GN 1024

// ---------------- scratch ----------------
__device__ __half g_Xh[MM*EE];
__device__ __half g_WT[5][EE*EE];   // 0=q 1=k 2=v 3=g 4=o, [n][k]
__device__ __half g_Qh[MM*EE];
__device__ __half g_Kh[MM*EE];
__device__ __half g_Vt[MM*EE];      // [b][h][d][tok]
__device__ float  g_G[MM*EE];
__device__ __half g_Oh[MM*EE];

// ---------------- helpers ----------------
__device__ __forceinline__ uint32_t smem_u32(const void* p) {
    return (uint32_t)__cvta_generic_to_shared(p);
}
#define CP16(d_, s_) asm volatile("cp.async.cg.shared.global [%0],[%1],16;\n" :: "r"(d_), "l"(s_))
#define CPCOMMIT() asm volatile("cp.async.commit_group;\n")
#define CPWAIT1() asm volatile("cp.async.wait_group 1;\n")
#define CPWAIT0() asm volatile("cp.async.wait_group 0;\n")

__device__ __forceinline__ void mma16(float* d, const uint32_t* a, const uint32_t* b) {
    asm volatile(
        "mma.sync.aligned.m16n8k16.row.col.f32.f16.f16.f32 "
        "{%0,%1,%2,%3}, {%4,%5,%6,%7}, {%8,%9}, {%0,%1,%2,%3};"
        : "+f"(d[0]), "+f"(d[1]), "+f"(d[2]), "+f"(d[3])
        : "r"(a[0]), "r"(a[1]), "r"(a[2]), "r"(a[3]), "r"(b[0]), "r"(b[1]));
}
__device__ __forceinline__ uint32_t h2u(float x, float y) {
    __half2 h = __floats2half2_rn(x, y);
    return *(uint32_t*)&h;
}

// ---------------- prep ----------------
__global__ void prep_x(const float* __restrict__ x) {
    int i = blockIdx.x * 256 + threadIdx.x;
    float2 v = ((const float2*)x)[i];
    ((__half2*)g_Xh)[i] = __floats2half2_rn(v.x, v.y);
}
__global__ void prep_w(const float* Wq, const float* Wk, const float* Wv,
                       const float* Wg, const float* Wo) {
    __shared__ float t[32][33];
    int z = blockIdx.z;
    const float* W = z==0?Wq : z==1?Wk : z==2?Wv : z==3?Wg : Wo;
    __half* D = g_WT[z];
    int n0 = blockIdx.x*32, k0 = blockIdx.y*32;
    int tx = threadIdx.x, ty = threadIdx.y;
#pragma unroll
    for (int j = 0; j < 4; ++j)
        t[ty + j*8][tx] = W[(size_t)(k0 + ty + j*8)*GN + n0 + tx];
    __syncthreads();
#pragma unroll
    for (int j = 0; j < 4; ++j)
        D[(size_t)(n0 + ty + j*8)*GK + k0 + tx] = __float2half_rn(t[tx][ty + j*8]);
}

// ---------------- GEMM core ----------------
#define AST 72
#define TILE_H (128*AST)
#define GEMM_SMEM (4*TILE_H*2)

__device__ __forceinline__ void gemm_core(
    const __half* __restrict__ A, const __half* __restrict__ Bt,
    const float* __restrict__ bias, float* __restrict__ fC,
    __half* __restrict__ hC, int mode)
{
    extern __shared__ char smp[];
    __half* As = (__half*)smp;
    __half* Bs = (__half*)smp + 2*TILE_H;

    const int tid = threadIdx.x, lane = tid & 31, wid = tid >> 5;
    const int wm = wid >> 1, wn = wid & 1, g = lane >> 2, c = lane & 3;
    const int row0 = blockIdx.y*128, col0 = blockIdx.x*128;

    float acc[4][8][4];
#pragma unroll
    for (int mi = 0; mi < 4; ++mi)
#pragma unroll
        for (int ni = 0; ni < 8; ++ni) {
            acc[mi][ni][0]=0.f; acc[mi][ni][1]=0.f; acc[mi][ni][2]=0.f; acc[mi][ni][3]=0.f;
        }

    {
#pragma unroll
        for (int u = 0; u < 8; ++u) {
            int idx = tid + u*128, m = idx >> 3, ko = (idx & 7)*8;
            CP16(smem_u32(&As[m*AST + ko]), &A[(size_t)(row0+m)*GK + ko]);
            CP16(smem_u32(&Bs[m*AST + ko]), &Bt[(size_t)(col0+m)*GK + ko]);
        }
        CPCOMMIT();
    }

#pragma unroll 1
    for (int it = 0; it < 16; ++it) {
        if (it < 15) {
            int buf = (it+1) & 1, k0 = (it+1)*64;
#pragma unroll
            for (int u = 0; u < 8; ++u) {
                int idx = tid + u*128, m = idx >> 3, ko = (idx & 7)*8;
                CP16(smem_u32(&As[buf*TILE_H + m*AST + ko]), &A[(size_t)(row0+m)*GK + k0 + ko]);
                CP16(smem_u32(&Bs[buf*TILE_H + m*AST + ko]), &Bt[(size_t)(col0+m)*GK + k0 + ko]);
            }
            CPCOMMIT();
            CPWAIT1();
        } else {
            CPWAIT0();
        }
        __syncthreads();
        const __half* Ab = &As[(it & 1)*TILE_H];
        const __half* Bb = &Bs[(it & 1)*TILE_H];
#pragma unroll
        for (int ks = 0; ks < 4; ++ks) {
            int kb = ks*16;
            uint32_t a[4][4];
#pragma unroll
            for (int mi = 0; mi < 4; ++mi) {
                int r = wm*64 + mi*16 + g;
                a[mi][0] = *(const uint32_t*)&Ab[r*AST + kb + 2*c];
                a[mi][1] = *(const uint32_t*)&Ab[(r+8)*AST + kb + 2*c];
                a[mi][2] = *(const uint32_t*)&Ab[r*AST + kb + 8 + 2*c];
                a[mi][3] = *(const uint32_t*)&Ab[(r+8)*AST + kb + 8 + 2*c];
            }
#pragma unroll
            for (int ni = 0; ni < 8; ++ni) {
                int n = wn*64 + ni*8 + g;
                uint32_t b[2];
                b[0] = *(const uint32_t*)&Bb[n*AST + kb + 2*c];
                b[1] = *(const uint32_t*)&Bb[n*AST + kb + 8 + 2*c];
#pragma unroll
                for (int mi = 0; mi < 4; ++mi) mma16(acc[mi][ni], a[mi], b);
            }
        }
        __syncthreads();
    }

#pragma unroll
    for (int mi = 0; mi < 4; ++mi) {
#pragma unroll
        for (int ni = 0; ni < 8; ++ni) {
            int r = row0 + wm*64 + mi*16 + g;
            int col = col0 + wn*64 + ni*8 + 2*c;
            float b0 = 0.f, b1 = 0.f;
            if (bias) { b0 = bias[col]; b1 = bias[col+1]; }
            float v0 = acc[mi][ni][0]+b0, v1 = acc[mi][ni][1]+b1;
            float v2 = acc[mi][ni][2]+b0, v3 = acc[mi][ni][3]+b1;
            if (mode == 0) { v0*=SCALE; v1*=SCALE; v2*=SCALE; v3*=SCALE; }
            if (mode >= 3) {
                *(float2*)&fC[(size_t)r*GN + col] = make_float2(v0, v1);
                *(float2*)&fC[(size_t)(r+8)*GN + col] = make_float2(v2, v3);
            } else if (mode == 2) {
                int bi = r >> 11, tok = r & 2047, hh = col >> 6, d = col & 63;
                __half* Vb = &g_Vt[(size_t)((bi*HH + hh)*DD) * SS];
                Vb[(size_t)d*SS + tok]       = __float2half_rn(v0);
                Vb[(size_t)(d+1)*SS + tok]   = __float2half_rn(v1);
                Vb[(size_t)d*SS + tok+8]     = __float2half_rn(v2);
                Vb[(size_t)(d+1)*SS + tok+8] = __float2half_rn(v3);
            } else {
                *(__half2*)&hC[(size_t)r*GN + col] = __floats2half2_rn(v0, v1);
                *(__half2*)&hC[(size_t)(r+8)*GN + col] = __floats2half2_rn(v2, v3);
            }
        }
    }
}

__global__ __launch_bounds__(128) void gemm_qkvg(
    const float* bq, const float* bk, const float* bv)
{
    int z = blockIdx.z;
    const float* bias = z==0?bq : z==1?bk : z==2?bv : nullptr;
    float* fC = (z == 3) ? g_G : nullptr;
    __half* hC = z==0?g_Qh : z==1?g_Kh : nullptr;
    gemm_core(g_Xh, g_WT[z], bias, fC, hC, z);
}
__global__ __launch_bounds__(128) void gemm_out(const float* bo, float* out)
{
    gemm_core(g_Oh, g_WT[4], bo, out, nullptr, 4);
}

// ---------------- Attention: register-P fp16 flash + cp.async pipeline ----
#define KST 72

__global__ __launch_bounds__(128) void attn_h(const unsigned char* __restrict__ mask)
{
    __shared__ __half Qs[64*KST];
    __shared__ __half Ks[2][64*KST];
    __shared__ __half Vs[2][64*KST];
    __shared__ unsigned char mskb[2][64];

    const int tid = threadIdx.x, lane = tid & 31, wid = tid >> 5;
    const int g = lane >> 2, c = lane & 3;
    const int h = blockIdx.y, b = blockIdx.z;
    const int q0 = blockIdx.x*64, hoff = h*DD;
    const int wrow = wid*16;
    const __half* Kg = &g_Kh[(size_t)b*SS*EE + hoff];
    const __half* Vg = &g_Vt[(size_t)(b*HH + h)*DD*SS];

    auto issue = [&](int tt) {
        int buf = tt & 1;
        int k0g = (tt >> 4)*1024 + (tt & 15)*64;
#pragma unroll
        for (int u = 0; u < 4; ++u) {
            int idx = tid + u*128, r = idx >> 3, ko = (idx & 7)*8;
            CP16(smem_u32(&Ks[buf][r*KST + ko]), &Kg[(size_t)(k0g + r)*EE + ko]);
            CP16(smem_u32(&Vs[buf][r*KST + ko]), &Vg[(size_t)r*SS + k0g + ko]);
        }
        if (tid < 4)
            CP16(smem_u32(&mskb[buf][tid*16]), &mask[(size_t)b*SS + k0g + tid*16]);
        CPCOMMIT();
    };

    // prologue: Q tile + (p0,t0) K/V in the same cp.async group
#pragma unroll
    for (int u = 0; u < 4; ++u) {
        int idx = tid + u*128, r = idx >> 3, ko = (idx & 7)*8;
        CP16(smem_u32(&Qs[r*KST + ko]), &g_Qh[(size_t)(b*SS + q0 + r)*EE + hoff + ko]);
    }
    issue(0);

    float fin[8][4], o[8][4];
    float l0 = 0.f, l1 = 0.f;
#pragma unroll
    for (int ni = 0; ni < 8; ++ni) {
        fin[ni][0]=0.f; fin[ni][1]=0.f; fin[ni][2]=0.f; fin[ni][3]=0.f;
        o[ni][0]=0.f;  o[ni][1]=0.f;  o[ni][2]=0.f;  o[ni][3]=0.f;
    }

#pragma unroll 1
    for (int tt = 0; tt < 32; ++tt) {
        if (tt < 31) { issue(tt + 1); CPWAIT1(); } else { CPWAIT0(); }
        __syncthreads();
        const __half* Kb = Ks[tt & 1];
        const __half* Vb = Vs[tt & 1];
        const unsigned char* mb = mskb[tt & 1];

        // ---- scores = Q @ K^T (Q pre-scaled in projection) ----
        float s[8][4];
#pragma unroll
        for (int ni = 0; ni < 8; ++ni) { s[ni][0]=0.f; s[ni][1]=0.f; s[ni][2]=0.f; s[ni][3]=0.f; }
#pragma unroll
        for (int ks = 0; ks < 4; ++ks) {
            int kb = ks*16;
            uint32_t a[4];
            int r = wrow + g;
            a[0] = *(const uint32_t*)&Qs[r*KST + kb + 2*c];
            a[1] = *(const uint32_t*)&Qs[(r+8)*KST + kb + 2*c];
            a[2] = *(const uint32_t*)&Qs[r*KST + kb + 8 + 2*c];
            a[3] = *(const uint32_t*)&Qs[(r+8)*KST + kb + 8 + 2*c];
#pragma unroll
            for (int ni = 0; ni < 8; ++ni) {
                int n = ni*8 + g;
                uint32_t bf[2];
                bf[0] = *(const uint32_t*)&Kb[n*KST + kb + 2*c];
                bf[1] = *(const uint32_t*)&Kb[n*KST + kb + 8 + 2*c];
                mma16(s[ni], a, bf);
            }
        }

        // ---- exp + row-sum (no max subtraction; logits bounded) ----
        float rs0 = 0.f, rs1 = 0.f;
#pragma unroll
        for (int ni = 0; ni < 8; ++ni) {
            float m0 = mb[ni*8 + 2*c]     ? -1e30f : 0.f;
            float m1 = mb[ni*8 + 2*c + 1] ? -1e30f : 0.f;
            s[ni][0] = __expf(s[ni][0] + m0);
            s[ni][1] = __expf(s[ni][1] + m1);
            s[ni][2] = __expf(s[ni][2] + m0);
            s[ni][3] = __expf(s[ni][3] + m1);
            rs0 += s[ni][0] + s[ni][1];
            rs1 += s[ni][2] + s[ni][3];
        }
        rs0 += __shfl_xor_sync(0xffffffffu, rs0, 1);
        rs0 += __shfl_xor_sync(0xffffffffu, rs0, 2);
        rs1 += __shfl_xor_sync(0xffffffffu, rs1, 1);
        rs1 += __shfl_xor_sync(0xffffffffu, rs1, 2);
        l0 += rs0; l1 += rs1;

        // ---- o += P @ V^T, P converted to A-frags in registers ----
#pragma unroll
        for (int kc = 0; kc < 4; ++kc) {
            uint32_t ap[4];
            ap[0] = h2u(s[2*kc][0],   s[2*kc][1]);
            ap[1] = h2u(s[2*kc][2],   s[2*kc][3]);
            ap[2] = h2u(s[2*kc+1][0], s[2*kc+1][1]);
            ap[3] = h2u(s[2*kc+1][2], s[2*kc+1][3]);
#pragma unroll
            for (int ni = 0; ni < 8; ++ni) {
                int n = ni*8 + g;
                uint32_t bf[2];
                bf[0] = *(const uint32_t*)&Vb[n*KST + kc*16 + 2*c];
                bf[1] = *(const uint32_t*)&Vb[n*KST + kc*16 + 8 + 2*c];
                mma16(o[ni], ap, bf);
            }
        }
        __syncthreads();   // reads of buf tt&1 done before issue(tt+2) overwrites

        // ---- partition boundary: fold normalized result, reset ----
        if ((tt & 15) == 15) {
            float pw = (tt >> 4) ? 1.0f : 0.5f;
            float inv0 = pw / l0, inv1 = pw / l1;
#pragma unroll
            for (int ni = 0; ni < 8; ++ni) {
                fin[ni][0] += o[ni][0]*inv0; fin[ni][1] += o[ni][1]*inv0;
                fin[ni][2] += o[ni][2]*inv1; fin[ni][3] += o[ni][3]*inv1;
                o[ni][0]=0.f; o[ni][1]=0.f; o[ni][2]=0.f; o[ni][3]=0.f;
            }
            l0 = 0.f; l1 = 0.f;
        }
    }

    // ---- epilogue: gate, write half ----
    const int r0 = q0 + wrow + g, r1 = r0 + 8;
#pragma unroll
    for (int ni = 0; ni < 8; ++ni) {
        int col = hoff + ni*8 + 2*c;
        size_t i0 = (size_t)(b*SS + r0)*EE + col;
        size_t i1 = (size_t)(b*SS + r1)*EE + col;
        float v0 = fin[ni][0], v1 = fin[ni][1], v2 = fin[ni][2], v3 = fin[ni][3];
        if (r0 >= 1) {
            float2 gv = *(const float2*)&g_G[i0];
            v0 *= 1.f/(1.f + __expf(-gv.x));
            v1 *= 1.f/(1.f + __expf(-gv.y));
        }
        float2 gw = *(const float2*)&g_G[i1];
        v2 *= 1.f/(1.f + __expf(-gw.x));
        v3 *= 1.f/(1.f + __expf(-gw.y));
        *(__half2*)&g_Oh[i0] = __floats2half2_rn(v0, v1);
        *(__half2*)&g_Oh[i1] = __floats2half2_rn(v2, v3);
    }
}

// ---------------- launch ----------------
extern "C" void kernel_launch(void* const* d_in, const int* in_sizes, int n_in,
                              void* d_out, int out_size)
{
    const float* x  = (const float*)d_in[0];
    const float* Wq = (const float*)d_in[1];
    const float* bq = (const float*)d_in[2];
    const float* Wk = (const float*)d_in[3];
    const float* bk = (const float*)d_in[4];
    const float* Wv = (const float*)d_in[5];
    const float* bv = (const float*)d_in[6];
    const float* Wo = (const float*)d_in[7];
    const float* bo = (const float*)d_in[8];
    const float* Wg = (const float*)d_in[9];
    const unsigned char* mask = (const unsigned char*)d_in[10];
    float* out = (float*)d_out;

    static int attr_set = 0;
    if (!attr_set) {
        cudaFuncSetAttribute(gemm_qkvg, cudaFuncAttributeMaxDynamicSharedMemorySize, GEMM_SMEM);
        cudaFuncSetAttribute(gemm_out,  cudaFuncAttributeMaxDynamicSharedMemorySize, GEMM_SMEM);
        attr_set = 1;
    }

    prep_x<<<MM*EE/512, 256>>>(x);
    prep_w<<<dim3(32, 32, 5), dim3(32, 8)>>>(Wq, Wk, Wv, Wg, Wo);
    gemm_qkvg<<<dim3(8, 32, 4), 128, GEMM_SMEM>>>(bq, bk, bv);
    attn_h<<<dim3(SS/64, HH, BB), 128>>>(mask);
    gemm_out<<<dim3(8, 32), 128, GEMM_SMEM>>>(bo, out);
}

// round 8
// speedup vs baseline: 2.6538x; 1.0726x over previous
#include <cuda_runtime.h>
#include <cuda_fp16.h>
#include <cstdint>

#define BB 2
#define SS 2048
#define EE 1024
#define HH 16
#define DD 64
#define MM (BB*SS)
#define SCALE 0.125f
#define LOG2E 1.44269504f
#define GK 1024
#define GN 1024

// ---------------- scratch ----------------
__device__ __half g_Xh[MM*EE];
__device__ __half g_WT[5][EE*EE];   // 0=q 1=k 2=v 3=g 4=o, [n][k]
__device__ __half g_Qh[MM*EE];
__device__ __half g_Kh[MM*EE];
__device__ __half g_Vt[MM*EE];      // [b][h][d][tok]
__device__ __half g_Gh[MM*EE];      // sigmoid(gate), half
__device__ __half g_O0h[MM*EE];
__device__ __half g_O1h[MM*EE];
__device__ __half g_Oh[MM*EE];

// ---------------- helpers ----------------
__device__ __forceinline__ uint32_t smem_u32(const void* p) {
    return (uint32_t)__cvta_generic_to_shared(p);
}
#define CP16(d_, s_) asm volatile("cp.async.cg.shared.global [%0],[%1],16;\n" :: "r"(d_), "l"(s_))
#define CPCOMMIT() asm volatile("cp.async.commit_group;\n")
#define CPWAIT1() asm volatile("cp.async.wait_group 1;\n")
#define CPWAIT0() asm volatile("cp.async.wait_group 0;\n")

__device__ __forceinline__ void mma16(float* d, const uint32_t* a, const uint32_t* b) {
    asm volatile(
        "mma.sync.aligned.m16n8k16.row.col.f32.f16.f16.f32 "
        "{%0,%1,%2,%3}, {%4,%5,%6,%7}, {%8,%9}, {%0,%1,%2,%3};"
        : "+f"(d[0]), "+f"(d[1]), "+f"(d[2]), "+f"(d[3])
        : "r"(a[0]), "r"(a[1]), "r"(a[2]), "r"(a[3]), "r"(b[0]), "r"(b[1]));
}
__device__ __forceinline__ uint32_t h2u(float x, float y) {
    __half2 h = __floats2half2_rn(x, y);
    return *(uint32_t*)&h;
}
__device__ __forceinline__ float fex2(float x) {
    float y; asm("ex2.approx.f32 %0, %1;" : "=f"(y) : "f"(x)); return y;
}

// ---------------- prep ----------------
__global__ void prep_x(const float* __restrict__ x) {
    int i = blockIdx.x * 256 + threadIdx.x;
    float2 v = ((const float2*)x)[i];
    ((__half2*)g_Xh)[i] = __floats2half2_rn(v.x, v.y);
}
__global__ void prep_w(const float* Wq, const float* Wk, const float* Wv,
                       const float* Wg, const float* Wo) {
    __shared__ float t[32][33];
    int z = blockIdx.z;
    const float* W = z==0?Wq : z==1?Wk : z==2?Wv : z==3?Wg : Wo;
    __half* D = g_WT[z];
    int n0 = blockIdx.x*32, k0 = blockIdx.y*32;
    int tx = threadIdx.x, ty = threadIdx.y;
#pragma unroll
    for (int j = 0; j < 4; ++j)
        t[ty + j*8][tx] = W[(size_t)(k0 + ty + j*8)*GN + n0 + tx];
    __syncthreads();
#pragma unroll
    for (int j = 0; j < 4; ++j)
        D[(size_t)(n0 + ty + j*8)*GK + k0 + tx] = __float2half_rn(t[tx][ty + j*8]);
}
__global__ void sum_o() {
    int i = blockIdx.x * 256 + threadIdx.x;
    ((__half2*)g_Oh)[i] = __hadd2(((const __half2*)g_O0h)[i], ((const __half2*)g_O1h)[i]);
}

// ---------------- GEMM core ----------------
#define AST 72
#define TILE_H (128*AST)
#define GEMM_SMEM (4*TILE_H*2)

__device__ __forceinline__ void gemm_core(
    const __half* __restrict__ A, const __half* __restrict__ Bt,
    const float* __restrict__ bias, float* __restrict__ fC,
    __half* __restrict__ hC, int mode)
{
    extern __shared__ char smp[];
    __half* As = (__half*)smp;
    __half* Bs = (__half*)smp + 2*TILE_H;

    const int tid = threadIdx.x, lane = tid & 31, wid = tid >> 5;
    const int wm = wid >> 1, wn = wid & 1, g = lane >> 2, c = lane & 3;
    const int row0 = blockIdx.y*128, col0 = blockIdx.x*128;

    float acc[4][8][4];
#pragma unroll
    for (int mi = 0; mi < 4; ++mi)
#pragma unroll
        for (int ni = 0; ni < 8; ++ni) {
            acc[mi][ni][0]=0.f; acc[mi][ni][1]=0.f; acc[mi][ni][2]=0.f; acc[mi][ni][3]=0.f;
        }

    {
#pragma unroll
        for (int u = 0; u < 8; ++u) {
            int idx = tid + u*128, m = idx >> 3, ko = (idx & 7)*8;
            CP16(smem_u32(&As[m*AST + ko]), &A[(size_t)(row0+m)*GK + ko]);
            CP16(smem_u32(&Bs[m*AST + ko]), &Bt[(size_t)(col0+m)*GK + ko]);
        }
        CPCOMMIT();
    }

#pragma unroll 1
    for (int it = 0; it < 16; ++it) {
        if (it < 15) {
            int buf = (it+1) & 1, k0 = (it+1)*64;
#pragma unroll
            for (int u = 0; u < 8; ++u) {
                int idx = tid + u*128, m = idx >> 3, ko = (idx & 7)*8;
                CP16(smem_u32(&As[buf*TILE_H + m*AST + ko]), &A[(size_t)(row0+m)*GK + k0 + ko]);
                CP16(smem_u32(&Bs[buf*TILE_H + m*AST + ko]), &Bt[(size_t)(col0+m)*GK + k0 + ko]);
            }
            CPCOMMIT();
            CPWAIT1();
        } else {
            CPWAIT0();
        }
        __syncthreads();
        const __half* Ab = &As[(it & 1)*TILE_H];
        const __half* Bb = &Bs[(it & 1)*TILE_H];
#pragma unroll
        for (int ks = 0; ks < 4; ++ks) {
            int kb = ks*16;
            uint32_t a[4][4];
#pragma unroll
            for (int mi = 0; mi < 4; ++mi) {
                int r = wm*64 + mi*16 + g;
                a[mi][0] = *(const uint32_t*)&Ab[r*AST + kb + 2*c];
                a[mi][1] = *(const uint32_t*)&Ab[(r+8)*AST + kb + 2*c];
                a[mi][2] = *(const uint32_t*)&Ab[r*AST + kb + 8 + 2*c];
                a[mi][3] = *(const uint32_t*)&Ab[(r+8)*AST + kb + 8 + 2*c];
            }
#pragma unroll
            for (int ni = 0; ni < 8; ++ni) {
                int n = wn*64 + ni*8 + g;
                uint32_t b[2];
                b[0] = *(const uint32_t*)&Bb[n*AST + kb + 2*c];
                b[1] = *(const uint32_t*)&Bb[n*AST + kb + 8 + 2*c];
#pragma unroll
                for (int mi = 0; mi < 4; ++mi) mma16(acc[mi][ni], a[mi], b);
            }
        }
        __syncthreads();
    }

#pragma unroll
    for (int mi = 0; mi < 4; ++mi) {
#pragma unroll
        for (int ni = 0; ni < 8; ++ni) {
            int r = row0 + wm*64 + mi*16 + g;
            int col = col0 + wn*64 + ni*8 + 2*c;
            float b0 = 0.f, b1 = 0.f;
            if (bias) { b0 = bias[col]; b1 = bias[col+1]; }
            float v0 = acc[mi][ni][0]+b0, v1 = acc[mi][ni][1]+b1;
            float v2 = acc[mi][ni][2]+b0, v3 = acc[mi][ni][3]+b1;
            if (mode == 0) {   // Q: fold SCALE and log2(e) for the ex2 softmax
                const float f = SCALE * LOG2E;
                v0*=f; v1*=f; v2*=f; v3*=f;
            }
            if (mode == 4) {
                *(float2*)&fC[(size_t)r*GN + col] = make_float2(v0, v1);
                *(float2*)&fC[(size_t)(r+8)*GN + col] = make_float2(v2, v3);
            } else if (mode == 3) {  // gate: store sigmoid as half
                float s0 = 1.f/(1.f+__expf(-v0)), s1 = 1.f/(1.f+__expf(-v1));
                float s2 = 1.f/(1.f+__expf(-v2)), s3 = 1.f/(1.f+__expf(-v3));
                *(__half2*)&hC[(size_t)r*GN + col] = __floats2half2_rn(s0, s1);
                *(__half2*)&hC[(size_t)(r+8)*GN + col] = __floats2half2_rn(s2, s3);
            } else if (mode == 2) {
                int bi = r >> 11, tok = r & 2047, hh = col >> 6, d = col & 63;
                __half* Vb = &g_Vt[(size_t)((bi*HH + hh)*DD) * SS];
                Vb[(size_t)d*SS + tok]       = __float2half_rn(v0);
                Vb[(size_t)(d+1)*SS + tok]   = __float2half_rn(v1);
                Vb[(size_t)d*SS + tok+8]     = __float2half_rn(v2);
                Vb[(size_t)(d+1)*SS + tok+8] = __float2half_rn(v3);
            } else {
                *(__half2*)&hC[(size_t)r*GN + col] = __floats2half2_rn(v0, v1);
                *(__half2*)&hC[(size_t)(r+8)*GN + col] = __floats2half2_rn(v2, v3);
            }
        }
    }
}

__global__ __launch_bounds__(128) void gemm_qkvg(
    const float* bq, const float* bk, const float* bv)
{
    int z = blockIdx.z;
    const float* bias = z==0?bq : z==1?bk : z==2?bv : nullptr;
    __half* hC = z==0?g_Qh : z==1?g_Kh : z==2?nullptr : g_Gh;
    gemm_core(g_Xh, g_WT[z], bias, nullptr, hC, z);
}
__global__ __launch_bounds__(128) void gemm_out(const float* bo, float* out)
{
    gemm_core(g_Oh, g_WT[4], bo, out, nullptr, 4);
}

// ---------------- Attention: mi=2 register-P flash, one partition/block ----
// Grid (S/128, H, B*2). 128 threads (4 warps), warp = 32 q rows, 64-key tiles.
#define KST 72
#define Q_OFF 0                       // halves: Qs[128][KST]
#define K_OFF (128*KST)               // Ks[2][64][KST]
#define V_OFF (K_OFF + 2*64*KST)      // Vs[2][64][KST]
#define MSK_OFF_B ((V_OFF + 2*64*KST)*2)   // byte offset of mask[2][64]
#define ATT_SMEM (MSK_OFF_B + 128)

__global__ __launch_bounds__(128) void attn_h(const unsigned char* __restrict__ mask)
{
    extern __shared__ char smc[];
    __half* Qs = (__half*)smc + Q_OFF;
    __half* Ks = (__half*)smc + K_OFF;
    __half* Vs = (__half*)smc + V_OFF;
    unsigned char* mskb = (unsigned char*)smc + MSK_OFF_B;

    const int tid = threadIdx.x, lane = tid & 31, wid = tid >> 5;
    const int g = lane >> 2, c = lane & 3;
    const int h = blockIdx.y, z = blockIdx.z;
    const int b = z >> 1, p = z & 1;
    const int q0 = blockIdx.x*128, hoff = h*DD;
    const int kbase = p*1024;
    const float pw = p ? 1.0f : 0.5f;
    const int wrow = wid*32;
    const __half* Kg = &g_Kh[(size_t)b*SS*EE + hoff];
    const __half* Vg = &g_Vt[(size_t)(b*HH + h)*DD*SS];

    auto issue = [&](int t) {
        int buf = t & 1, k0g = kbase + t*64;
#pragma unroll
        for (int u = 0; u < 4; ++u) {
            int idx = tid + u*128, r = idx >> 3, ko = (idx & 7)*8;
            CP16(smem_u32(&Ks[buf*64*KST + r*KST + ko]), &Kg[(size_t)(k0g + r)*EE + ko]);
            CP16(smem_u32(&Vs[buf*64*KST + r*KST + ko]), &Vg[(size_t)r*SS + k0g + ko]);
        }
        if (tid < 4)
            CP16(smem_u32(&mskb[(t & 1)*64 + tid*16]), &mask[(size_t)b*SS + k0g + tid*16]);
        CPCOMMIT();
    };

    // prologue: Q tile (128 rows) + tile 0 K/V in the same group
#pragma unroll
    for (int u = 0; u < 8; ++u) {
        int idx = tid + u*128, r = idx >> 3, ko = (idx & 7)*8;
        CP16(smem_u32(&Qs[r*KST + ko]), &g_Qh[(size_t)(b*SS + q0 + r)*EE + hoff + ko]);
    }
    issue(0);

    float o[2][8][4];
    float l[2][2] = {{0.f,0.f},{0.f,0.f}};
#pragma unroll
    for (int mi = 0; mi < 2; ++mi)
#pragma unroll
        for (int ni = 0; ni < 8; ++ni) {
            o[mi][ni][0]=0.f; o[mi][ni][1]=0.f; o[mi][ni][2]=0.f; o[mi][ni][3]=0.f;
        }

#pragma unroll 1
    for (int t = 0; t < 16; ++t) {
        if (t < 15) { issue(t + 1); CPWAIT1(); } else { CPWAIT0(); }
        __syncthreads();
        const __half* Kb = &Ks[(t & 1)*64*KST];
        const __half* Vb = &Vs[(t & 1)*64*KST];
        const unsigned char* mb = &mskb[(t & 1)*64];

        // ---- scores = Q @ K^T (Q pre-scaled by SCALE*log2e) ----
        float s[2][8][4];
#pragma unroll
        for (int mi = 0; mi < 2; ++mi)
#pragma unroll
            for (int ni = 0; ni < 8; ++ni) {
                s[mi][ni][0]=0.f; s[mi][ni][1]=0.f; s[mi][ni][2]=0.f; s[mi][ni][3]=0.f;
            }
#pragma unroll
        for (int ks = 0; ks < 4; ++ks) {
            int kb = ks*16;
            uint32_t a[2][4];
#pragma unroll
            for (int mi = 0; mi < 2; ++mi) {
                int r = wrow + mi*16 + g;
                a[mi][0] = *(const uint32_t*)&Qs[r*KST + kb + 2*c];
                a[mi][1] = *(const uint32_t*)&Qs[(r+8)*KST + kb + 2*c];
                a[mi][2] = *(const uint32_t*)&Qs[r*KST + kb + 8 + 2*c];
                a[mi][3] = *(const uint32_t*)&Qs[(r+8)*KST + kb + 8 + 2*c];
            }
#pragma unroll
            for (int ni = 0; ni < 8; ++ni) {
                int n = ni*8 + g;
                uint32_t bf[2];
                bf[0] = *(const uint32_t*)&Kb[n*KST + kb + 2*c];
                bf[1] = *(const uint32_t*)&Kb[n*KST + kb + 8 + 2*c];
                mma16(s[0][ni], a[0], bf);
                mma16(s[1][ni], a[1], bf);
            }
        }

        // ---- exp2 + row-sums (no max subtraction; logits bounded) ----
#pragma unroll
        for (int mi = 0; mi < 2; ++mi) {
            float rs0 = 0.f, rs1 = 0.f;
#pragma unroll
            for (int ni = 0; ni < 8; ++ni) {
                float m0 = mb[ni*8 + 2*c]     ? -1e30f : 0.f;
                float m1 = mb[ni*8 + 2*c + 1] ? -1e30f : 0.f;
                s[mi][ni][0] = fex2(s[mi][ni][0] + m0);
                s[mi][ni][1] = fex2(s[mi][ni][1] + m1);
                s[mi][ni][2] = fex2(s[mi][ni][2] + m0);
                s[mi][ni][3] = fex2(s[mi][ni][3] + m1);
                rs0 += s[mi][ni][0] + s[mi][ni][1];
                rs1 += s[mi][ni][2] + s[mi][ni][3];
            }
            rs0 += __shfl_xor_sync(0xffffffffu, rs0, 1);
            rs0 += __shfl_xor_sync(0xffffffffu, rs0, 2);
            rs1 += __shfl_xor_sync(0xffffffffu, rs1, 1);
            rs1 += __shfl_xor_sync(0xffffffffu, rs1, 2);
            l[mi][0] += rs0; l[mi][1] += rs1;
        }

        // ---- o += P @ V^T, P packed to A-frags in registers ----
#pragma unroll
        for (int kc = 0; kc < 4; ++kc) {
            uint32_t ap[2][4];
#pragma unroll
            for (int mi = 0; mi < 2; ++mi) {
                ap[mi][0] = h2u(s[mi][2*kc][0],   s[mi][2*kc][1]);
                ap[mi][1] = h2u(s[mi][2*kc][2],   s[mi][2*kc][3]);
                ap[mi][2] = h2u(s[mi][2*kc+1][0], s[mi][2*kc+1][1]);
                ap[mi][3] = h2u(s[mi][2*kc+1][2], s[mi][2*kc+1][3]);
            }
#pragma unroll
            for (int ni = 0; ni < 8; ++ni) {
                int n = ni*8 + g;
                uint32_t bf[2];
                bf[0] = *(const uint32_t*)&Vb[n*KST + kc*16 + 2*c];
                bf[1] = *(const uint32_t*)&Vb[n*KST + kc*16 + 8 + 2*c];
                mma16(o[0][ni], ap[0], bf);
                mma16(o[1][ni], ap[1], bf);
            }
        }
        __syncthreads();   // reads of buf t&1 done before issue(t+2) overwrites
    }

    // ---- epilogue: normalize, gate (pre-sigmoided half), write half ----
    __half* Op = p ? g_O1h : g_O0h;
#pragma unroll
    for (int mi = 0; mi < 2; ++mi) {
        const int r0 = q0 + wrow + mi*16 + g, r1 = r0 + 8;
        const float inv0 = pw / l[mi][0], inv1 = pw / l[mi][1];
#pragma unroll
        for (int ni = 0; ni < 8; ++ni) {
            int col = hoff + ni*8 + 2*c;
            size_t i0 = (size_t)(b*SS + r0)*EE + col;
            size_t i1 = (size_t)(b*SS + r1)*EE + col;
            float v0 = o[mi][ni][0]*inv0, v1 = o[mi][ni][1]*inv0;
            float v2 = o[mi][ni][2]*inv1, v3 = o[mi][ni][3]*inv1;
            if (r0 >= 1) {
                __half2 gh = *(const __half2*)&g_Gh[i0];
                v0 *= __half2float(gh.x);
                v1 *= __half2float(gh.y);
            }
            __half2 gw = *(const __half2*)&g_Gh[i1];
            v2 *= __half2float(gw.x);
            v3 *= __half2float(gw.y);
            *(__half2*)&Op[i0] = __floats2half2_rn(v0, v1);
            *(__half2*)&Op[i1] = __floats2half2_rn(v2, v3);
        }
    }
}

// ---------------- launch ----------------
extern "C" void kernel_launch(void* const* d_in, const int* in_sizes, int n_in,
                              void* d_out, int out_size)
{
    const float* x  = (const float*)d_in[0];
    const float* Wq = (const float*)d_in[1];
    const float* bq = (const float*)d_in[2];
    const float* Wk = (const float*)d_in[3];
    const float* bk = (const float*)d_in[4];
    const float* Wv = (const float*)d_in[5];
    const float* bv = (const float*)d_in[6];
    const float* Wo = (const float*)d_in[7];
    const float* bo = (const float*)d_in[8];
    const float* Wg = (const float*)d_in[9];
    const unsigned char* mask = (const unsigned char*)d_in[10];
    float* out = (float*)d_out;

    static int attr_set = 0;
    if (!attr_set) {
        cudaFuncSetAttribute(gemm_qkvg, cudaFuncAttributeMaxDynamicSharedMemorySize, GEMM_SMEM);
        cudaFuncSetAttribute(gemm_out,  cudaFuncAttributeMaxDynamicSharedMemorySize, GEMM_SMEM);
        cudaFuncSetAttribute(attn_h,    cudaFuncAttributeMaxDynamicSharedMemorySize, ATT_SMEM);
        attr_set = 1;
    }

    prep_x<<<MM*EE/512, 256>>>(x);
    prep_w<<<dim3(32, 32, 5), dim3(32, 8)>>>(Wq, Wk, Wv, Wg, Wo);
    gemm_qkvg<<<dim3(8, 32, 4), 128, GEMM_SMEM>>>(bq, bk, bv);
    attn_h<<<dim3(SS/128, HH, BB*2), 128, ATT_SMEM>>>(mask);
    sum_o<<<MM*EE/512, 256>>>();
    gemm_out<<<dim3(8, 32), 128, GEMM_SMEM>>>(bo, out);
}